// round 10
// baseline (speedup 1.0000x reference)
#include <cuda_runtime.h>

// Retrace: B=2048, T=512, D=16 (fp32). Single persistent kernel:
//   Phase 1: segmented affine scan — each (chain, segment) thread computes
//            carry_out = A*x + B and loss_seg(x) = sdd - 2x*sAd + x^2*sAA.
//   Grid barrier (all 1024 blocks co-resident: occ 8/SM * 148 = 1184 >= 1024).
//   Phase 2: first 256 blocks chain segments from L2, reduce, finalize.
//
// Inputs (metadata order):
//   0: Q [B,T,D]  1: expected_target_Q [B,T,D]  2: target_Q [B,T,D]
//   3: rewards [B,T,D]  4: target_policy_probs [B,T,D]  5: behaviour_policy_probs [B,T]
// Output: scalar fp32 = mean((Q[:, :-1] - q_ret)^2)

#define T_DIM 512
#define D_DIM 16
#define GAMMA 0.99f
#define BLOCK 128
#define SEG 4
#define SEGLEN 128                      // 511 = 4*128 - 1 (last segment: 127 steps)
#define NCHAINS (2048 * 16)             // 32768
#define NBLK ((NCHAINS * SEG) / BLOCK)  // 1024 blocks, single wave
#define NBLK2 (NCHAINS / BLOCK)         // 256 combine blocks
#define GROUP 6

__device__ float g_sAA[SEG * NCHAINS];
__device__ float g_sAd[SEG * NCHAINS];
__device__ float g_sdd[SEG * NCHAINS];
__device__ float g_A  [SEG * NCHAINS];
__device__ float g_B  [SEG * NCHAINS];
__device__ float g_x0 [NCHAINS];        // TQ[:, -1] stashed by phase 1
__device__ float g_partials[NBLK2];
// Monotonic counters: never reset -> safe across CUDA-graph replays.
__device__ unsigned int g_arrive;
__device__ unsigned int g_ticket;

__global__ __launch_bounds__(BLOCK, 8)   // regs <= 64 -> 8 blocks/SM -> co-residency
void retrace_fused(const float* __restrict__ Q,
                   const float* __restrict__ E,
                   const float* __restrict__ TQ,
                   const float* __restrict__ R,
                   const float* __restrict__ TPP,
                   const float* __restrict__ BPP,
                   float* __restrict__ out,
                   double inv_count)
{
    // ======================= Phase 1: segment summaries =======================
    {
        const int tid = blockIdx.x * BLOCK + threadIdx.x;
        const int cid = tid & (NCHAINS - 1);     // chain id (d fastest -> coalesced)
        const int s   = tid >> 15;               // segment id, 0..3
        const int b   = cid >> 4;
        const int d   = cid & 15;

        const int lo = s * SEGLEN;
        const int hi = (s == SEG - 1) ? (T_DIM - 2) : (lo + SEGLEN - 1);
        const int n  = hi - lo + 1;              // 128, or 127 for s=3

        const long base = (long)b * (T_DIM * D_DIM) + d;
        const float* pr  = R   + base + (long)hi * D_DIM;        // rewards[t]
        const float* pq  = Q   + base + (long)hi * D_DIM;        // Q[t]
        const float* pe  = E   + base + (long)(hi + 1) * D_DIM;  // E[t+1]
        const float* ptq = TQ  + base + (long)(hi + 1) * D_DIM;  // TQ[t+1]
        const float* ptp = TPP + base + (long)(hi + 1) * D_DIM;  // TPP[t+1]
        const float* pb  = BPP + (long)b * T_DIM + (hi + 1);     // BPP[t+1]

        if (s == SEG - 1)
            g_x0[cid] = ptq[0];                  // TQ[:, -1] (hi+1 == T-1)

        float A = 1.0f, Bv = 0.0f;
        float sAA = 0.0f, sAd = 0.0f, sdd = 0.0f;

        int i = 0;
        for (; i + GROUP <= n; i += GROUP) {
            float r[GROUP], qv[GROUP], e[GROUP], tq[GROUP], tp[GROUP], bp[GROUP];
            #pragma unroll
            for (int k = 0; k < GROUP; ++k) {
                const int o = (i + k) * D_DIM;
                r[k]  = pr [-o];
                qv[k] = pq [-o];
                e[k]  = pe [-o];
                tq[k] = ptq[-o];
                tp[k] = ptp[-o];
                bp[k] = pb [-(i + k)];
            }
            #pragma unroll
            for (int k = 0; k < GROUP; ++k) {
                float c  = __expf(fminf(tp[k] - bp[k], 0.0f));
                float m  = GAMMA * c;
                float t1 = fmaf(GAMMA, e[k], r[k]);      // r + g*e
                Bv = fmaf(m, Bv - tq[k], t1);            // B' = m*(B - tq) + t1
                A  = m * A;                              // A' = m*A
                float dv = qv[k] - Bv;                   // df = dv - A'*x
                sdd = fmaf(dv, dv, sdd);
                sAd = fmaf(A, dv, sAd);
                sAA = fmaf(A, A, sAA);
            }
        }
        for (; i < n; ++i) {                             // remainder (<= 2 steps)
            const int o = i * D_DIM;
            float c  = __expf(fminf(ptp[-o] - pb[-i], 0.0f));
            float m  = GAMMA * c;
            float t1 = fmaf(GAMMA, pe[-o], pr[-o]);
            Bv = fmaf(m, Bv - ptq[-o], t1);
            A  = m * A;
            float dv = pq[-o] - Bv;
            sdd = fmaf(dv, dv, sdd);
            sAd = fmaf(A, dv, sAd);
            sAA = fmaf(A, A, sAA);
        }

        const int idx = s * NCHAINS + cid;
        g_sAA[idx] = sAA;
        g_sAd[idx] = sAd;
        g_sdd[idx] = sdd;
        g_A[idx]   = A;
        g_B[idx]   = Bv;
    }

    // ===================== Grid barrier (monotonic counter) ===================
    __threadfence();                             // publish phase-1 writes
    __shared__ unsigned int s_target;
    __syncthreads();                             // all block threads done above
    if (threadIdx.x == 0) {
        unsigned int t = atomicAdd(&g_arrive, 1u);
        s_target = (t / NBLK + 1u) * NBLK;       // end-count for THIS launch
    }
    __syncthreads();

    if (blockIdx.x >= NBLK2)                     // non-combine blocks: arrive & exit
        return;

    if (threadIdx.x == 0) {
        while (*(volatile unsigned int*)&g_arrive < s_target) { }
    }
    __syncthreads();
    __threadfence();                             // acquire phase-1 writes

    // ================= Phase 2: chain segments, reduce, finalize ==============
    const int cid = blockIdx.x * BLOCK + threadIdx.x;

    // Front-batch all 21 loads (L2-resident), then run the dependent chain.
    float aa[SEG], ad[SEG], dd[SEG], Av[SEG], Bs[SEG];
    #pragma unroll
    for (int s = 0; s < SEG; ++s) {
        const int idx = s * NCHAINS + cid;
        aa[s] = g_sAA[idx];
        ad[s] = g_sAd[idx];
        dd[s] = g_sdd[idx];
        Av[s] = g_A[idx];
        Bs[s] = g_B[idx];
    }
    float x = g_x0[cid];

    float loss = 0.0f;
    #pragma unroll
    for (int s = SEG - 1; s >= 0; --s) {         // latest times first
        loss += fmaf(x, fmaf(x, aa[s], -2.0f * ad[s]), dd[s]);
        x = fmaf(Av[s], x, Bs[s]);
    }

    // Deterministic block reduction.
    #pragma unroll
    for (int off = 16; off > 0; off >>= 1)
        loss += __shfl_xor_sync(0xFFFFFFFFu, loss, off);

    __shared__ float s_warp[BLOCK / 32];
    const int lane = threadIdx.x & 31;
    const int wid  = threadIdx.x >> 5;
    if (lane == 0) s_warp[wid] = loss;
    __syncthreads();

    __shared__ bool s_last;
    if (threadIdx.x == 0) {
        g_partials[blockIdx.x] = s_warp[0] + s_warp[1] + s_warp[2] + s_warp[3];
        __threadfence();
        unsigned int t = atomicAdd(&g_ticket, 1u);
        s_last = ((t % NBLK2) == NBLK2 - 1);     // monotonic across replays
    }
    __syncthreads();

    if (s_last) {
        __shared__ double s_d[BLOCK];
        double v = 0.0;
        for (int i = threadIdx.x; i < NBLK2; i += BLOCK)
            v += (double)g_partials[i];
        s_d[threadIdx.x] = v;
        __syncthreads();
        for (int stride = BLOCK >> 1; stride > 0; stride >>= 1) {
            if (threadIdx.x < stride) s_d[threadIdx.x] += s_d[threadIdx.x + stride];
            __syncthreads();
        }
        if (threadIdx.x == 0)
            out[0] = (float)(s_d[0] * inv_count);
    }
}

extern "C" void kernel_launch(void* const* d_in, const int* in_sizes, int n_in,
                              void* d_out, int out_size)
{
    const float* Q   = (const float*)d_in[0];
    const float* E   = (const float*)d_in[1];
    const float* TQ  = (const float*)d_in[2];
    const float* R   = (const float*)d_in[3];
    const float* TPP = (const float*)d_in[4];
    const float* BPP = (const float*)d_in[5];

    const int B = in_sizes[5] / T_DIM;           // 2048
    const double inv_count =
        1.0 / ((double)B * (double)(T_DIM - 1) * (double)D_DIM);

    retrace_fused<<<NBLK, BLOCK>>>(Q, E, TQ, R, TPP, BPP,
                                   (float*)d_out, inv_count);
}

// round 11
// speedup vs baseline: 1.0267x; 1.0267x over previous
#include <cuda_runtime.h>

// Retrace: B=2048, T=512, D=16 (fp32). Single persistent kernel:
//   Phase 1: segmented affine scan — each (chain, segment) thread computes
//            carry_out = A*x + B and loss_seg(x) = sdd - 2x*sAd + x^2*sAA.
//   Grid barrier (all 1024 blocks co-resident: occ 8/SM * 148 = 1184 >= 1024).
//   Phase 2: first 256 blocks chain segments from L2, reduce, finalize.
//
// Inputs (metadata order):
//   0: Q [B,T,D]  1: expected_target_Q [B,T,D]  2: target_Q [B,T,D]
//   3: rewards [B,T,D]  4: target_policy_probs [B,T,D]  5: behaviour_policy_probs [B,T]
// Output: scalar fp32 = mean((Q[:, :-1] - q_ret)^2)

#define T_DIM 512
#define D_DIM 16
#define GAMMA 0.99f
#define BLOCK 128
#define SEG 4
#define SEGLEN 128                      // 511 = 4*128 - 1 (last segment: 127 steps)
#define NCHAINS (2048 * 16)             // 32768
#define NBLK ((NCHAINS * SEG) / BLOCK)  // 1024 blocks, single wave
#define NBLK2 (NCHAINS / BLOCK)         // 256 combine blocks
#define GROUP 5

__device__ float g_sAA[SEG * NCHAINS];
__device__ float g_sAd[SEG * NCHAINS];
__device__ float g_sdd[SEG * NCHAINS];
__device__ float g_A  [SEG * NCHAINS];
__device__ float g_B  [SEG * NCHAINS];
__device__ float g_x0 [NCHAINS];        // TQ[:, -1] stashed by phase 1
__device__ float g_partials[NBLK2];
// Monotonic counters: never reset -> safe across CUDA-graph replays.
__device__ unsigned int g_arrive;
__device__ unsigned int g_ticket;

__global__ __launch_bounds__(BLOCK, 8)   // regs <= 64 -> 8 blocks/SM -> co-residency
void retrace_fused(const float* __restrict__ Q,
                   const float* __restrict__ E,
                   const float* __restrict__ TQ,
                   const float* __restrict__ R,
                   const float* __restrict__ TPP,
                   const float* __restrict__ BPP,
                   float* __restrict__ out,
                   double inv_count)
{
    // ======================= Phase 1: segment summaries =======================
    {
        const int tid = blockIdx.x * BLOCK + threadIdx.x;
        const int cid = tid & (NCHAINS - 1);     // chain id (d fastest -> coalesced)
        const int s   = tid >> 15;               // segment id, 0..3
        const int b   = cid >> 4;
        const int d   = cid & 15;

        const int lo = s * SEGLEN;
        const int hi = (s == SEG - 1) ? (T_DIM - 2) : (lo + SEGLEN - 1);
        const int n  = hi - lo + 1;              // 128, or 127 for s=3

        const long base = (long)b * (T_DIM * D_DIM) + d;
        // Running pointers: advanced by GROUP*D_DIM per group so every load
        // inside a group uses a compile-time immediate offset (-k*D_DIM).
        const float* pr  = R   + base + (long)hi * D_DIM;        // rewards[t]
        const float* pq  = Q   + base + (long)hi * D_DIM;        // Q[t]
        const float* pe  = E   + base + (long)(hi + 1) * D_DIM;  // E[t+1]
        const float* ptq = TQ  + base + (long)(hi + 1) * D_DIM;  // TQ[t+1]
        const float* ptp = TPP + base + (long)(hi + 1) * D_DIM;  // TPP[t+1]
        const float* pb  = BPP + (long)b * T_DIM + (hi + 1);     // BPP[t+1]

        if (s == SEG - 1)
            g_x0[cid] = ptq[0];                  // TQ[:, -1] (hi+1 == T-1)

        float A = 1.0f, Bv = 0.0f;
        float sAA = 0.0f, sAd = 0.0f, sdd = 0.0f;

        int i = 0;
        for (; i + GROUP <= n; i += GROUP) {
            float r[GROUP], qv[GROUP], e[GROUP], tq[GROUP], tp[GROUP], bp[GROUP];
            #pragma unroll
            for (int k = 0; k < GROUP; ++k) {    // immediate-offset LDGs
                r[k]  = pr [-k * D_DIM];
                qv[k] = pq [-k * D_DIM];
                e[k]  = pe [-k * D_DIM];
                tq[k] = ptq[-k * D_DIM];
                tp[k] = ptp[-k * D_DIM];
                bp[k] = pb [-k];
            }
            #pragma unroll
            for (int k = 0; k < GROUP; ++k) {
                float c  = __expf(fminf(tp[k] - bp[k], 0.0f));
                float m  = GAMMA * c;
                float t1 = fmaf(GAMMA, e[k], r[k]);      // r + g*e
                Bv = fmaf(m, Bv - tq[k], t1);            // B' = m*(B - tq) + t1
                A  = m * A;                              // A' = m*A
                float dv = qv[k] - Bv;                   // df = dv - A'*x
                sdd = fmaf(dv, dv, sdd);
                sAd = fmaf(A, dv, sAd);
                sAA = fmaf(A, A, sAA);
            }
            pr  -= GROUP * D_DIM;
            pq  -= GROUP * D_DIM;
            pe  -= GROUP * D_DIM;
            ptq -= GROUP * D_DIM;
            ptp -= GROUP * D_DIM;
            pb  -= GROUP;
        }
        for (; i < n; ++i) {                             // remainder (<= 4 steps)
            float c  = __expf(fminf(ptp[0] - pb[0], 0.0f));
            float m  = GAMMA * c;
            float t1 = fmaf(GAMMA, pe[0], pr[0]);
            Bv = fmaf(m, Bv - ptq[0], t1);
            A  = m * A;
            float dv = pq[0] - Bv;
            sdd = fmaf(dv, dv, sdd);
            sAd = fmaf(A, dv, sAd);
            sAA = fmaf(A, A, sAA);
            pr  -= D_DIM; pq -= D_DIM; pe -= D_DIM;
            ptq -= D_DIM; ptp -= D_DIM; pb -= 1;
        }

        const int idx = s * NCHAINS + cid;
        g_sAA[idx] = sAA;
        g_sAd[idx] = sAd;
        g_sdd[idx] = sdd;
        g_A[idx]   = A;
        g_B[idx]   = Bv;
    }

    // ===================== Grid barrier (monotonic counter) ===================
    __threadfence();                             // publish phase-1 writes
    __shared__ unsigned int s_target;
    __syncthreads();                             // all block threads done above
    if (threadIdx.x == 0) {
        unsigned int t = atomicAdd(&g_arrive, 1u);
        s_target = (t / NBLK + 1u) * NBLK;       // end-count for THIS launch
    }
    __syncthreads();

    if (blockIdx.x >= NBLK2)                     // non-combine blocks: arrive & exit
        return;

    if (threadIdx.x == 0) {
        while (*(volatile unsigned int*)&g_arrive < s_target) { }
    }
    __syncthreads();
    __threadfence();                             // acquire phase-1 writes

    // ================= Phase 2: chain segments, reduce, finalize ==============
    const int cid = blockIdx.x * BLOCK + threadIdx.x;

    // Front-batch all 21 loads (L2-resident), then run the dependent chain.
    float aa[SEG], ad[SEG], dd[SEG], Av[SEG], Bs[SEG];
    #pragma unroll
    for (int s = 0; s < SEG; ++s) {
        const int idx = s * NCHAINS + cid;
        aa[s] = g_sAA[idx];
        ad[s] = g_sAd[idx];
        dd[s] = g_sdd[idx];
        Av[s] = g_A[idx];
        Bs[s] = g_B[idx];
    }
    float x = g_x0[cid];

    float loss = 0.0f;
    #pragma unroll
    for (int s = SEG - 1; s >= 0; --s) {         // latest times first
        loss += fmaf(x, fmaf(x, aa[s], -2.0f * ad[s]), dd[s]);
        x = fmaf(Av[s], x, Bs[s]);
    }

    // Deterministic block reduction.
    #pragma unroll
    for (int off = 16; off > 0; off >>= 1)
        loss += __shfl_xor_sync(0xFFFFFFFFu, loss, off);

    __shared__ float s_warp[BLOCK / 32];
    const int lane = threadIdx.x & 31;
    const int wid  = threadIdx.x >> 5;
    if (lane == 0) s_warp[wid] = loss;
    __syncthreads();

    __shared__ bool s_last;
    if (threadIdx.x == 0) {
        g_partials[blockIdx.x] = s_warp[0] + s_warp[1] + s_warp[2] + s_warp[3];
        __threadfence();
        unsigned int t = atomicAdd(&g_ticket, 1u);
        s_last = ((t % NBLK2) == NBLK2 - 1);     // monotonic across replays
    }
    __syncthreads();

    if (s_last) {
        __shared__ double s_d[BLOCK];
        double v = 0.0;
        for (int i = threadIdx.x; i < NBLK2; i += BLOCK)
            v += (double)g_partials[i];
        s_d[threadIdx.x] = v;
        __syncthreads();
        for (int stride = BLOCK >> 1; stride > 0; stride >>= 1) {
            if (threadIdx.x < stride) s_d[threadIdx.x] += s_d[threadIdx.x + stride];
            __syncthreads();
        }
        if (threadIdx.x == 0)
            out[0] = (float)(s_d[0] * inv_count);
    }
}

extern "C" void kernel_launch(void* const* d_in, const int* in_sizes, int n_in,
                              void* d_out, int out_size)
{
    const float* Q   = (const float*)d_in[0];
    const float* E   = (const float*)d_in[1];
    const float* TQ  = (const float*)d_in[2];
    const float* R   = (const float*)d_in[3];
    const float* TPP = (const float*)d_in[4];
    const float* BPP = (const float*)d_in[5];

    const int B = in_sizes[5] / T_DIM;           // 2048
    const double inv_count =
        1.0 / ((double)B * (double)(T_DIM - 1) * (double)D_DIM);

    retrace_fused<<<NBLK, BLOCK>>>(Q, E, TQ, R, TPP, BPP,
                                   (float*)d_out, inv_count);
}